// round 1
// baseline (speedup 1.0000x reference)
#include <cuda_runtime.h>

#define BB 256   // batch
#define SS 256   // seq len / steps
#define EE 2     // encoder dim
#define DD 128   // decoder dim
#define GG 512   // 4*D gates

// Scratch (allowed: __device__ globals, no allocation)
__device__ __align__(16) float g_WhhT[DD * GG];  // [d][j]
__device__ float g_w1sum[SS];
__device__ float g_bias[GG];

__device__ __forceinline__ float tanh_fast(float x) {
    float y;
    asm("tanh.approx.f32 %0, %1;" : "=f"(y) : "f"(x));
    return y;
}

// ---------------------------------------------------------------------------
// Prep kernel: transpose W_hh, row-sum W1_w, fuse biases. One-time cost.
// ---------------------------------------------------------------------------
__global__ void prep_kernel(const float* __restrict__ W1_w,
                            const float* __restrict__ W_hh,
                            const float* __restrict__ b_ih,
                            const float* __restrict__ b_hh) {
    int blk = blockIdx.x;
    int t = threadIdx.x;
    if (blk < 256) {
        // transpose W_hh [512,128] -> g_WhhT [128,512]; coalesced read
        int idx = blk * 256 + t;      // 0..65535
        int j = idx >> 7;             // gate row 0..511
        int d = idx & 127;
        g_WhhT[d * GG + j] = W_hh[idx];
    } else {
        int lane = t & 31, w = t >> 5;
        // w1sum[s] = sum_j W1_w[s][j], warp-per-row coalesced
        for (int r = 0; r < 32; r++) {
            int s = w * 32 + r;
            float acc = 0.f;
            #pragma unroll
            for (int i = 0; i < 8; i++) acc += W1_w[s * SS + lane + 32 * i];
            #pragma unroll
            for (int off = 16; off; off >>= 1)
                acc += __shfl_xor_sync(0xffffffffu, acc, off);
            if (lane == 0) g_w1sum[s] = acc;
        }
        g_bias[t]       = b_ih[t]       + b_hh[t];
        g_bias[t + 256] = b_ih[t + 256] + b_hh[t + 256];
    }
}

// ---------------------------------------------------------------------------
// Main kernel: one CTA per batch element, 256 threads, loops 256 LSTM steps.
// ---------------------------------------------------------------------------
__global__ __launch_bounds__(256, 2)
void decoder_kernel(const float* __restrict__ enc,   // [B,S,E]
                    const float* __restrict__ W1_b,  // [S]
                    const float* __restrict__ W2_w,  // [S,2S]
                    const float* __restrict__ W2_b,  // [S]
                    const float* __restrict__ W_ih,  // [4D,E]
                    float* __restrict__ out)         // [S,B,D]
{
    __shared__ __align__(16) float4 sdat[SS];      // {a, w1sum, enc0, enc1}
    __shared__ __align__(16) float  ebuf[2 * SS];  // flattened encoder row
    __shared__ __align__(16) float4 red[DD];       // half-combine {Z,n0,n1,_}
    __shared__ float gates_s[GG];
    __shared__ __align__(16) float h_s[DD];
    __shared__ float c_s[DD];
    __shared__ float wred[4][2];
    __shared__ float ctx_s[2];

    const int b = blockIdx.x;
    const int t = threadIdx.x;
    const int lane = t & 31;
    const int warp = t >> 5;

    // ---- per-b init ----
    ebuf[t]       = enc[b * (2 * SS) + t];
    ebuf[t + 256] = enc[b * (2 * SS) + t + 256];
    if (t < DD) { h_s[t] = 0.f; c_s[t] = 0.f; }
    __syncthreads();

    // a[s] = encflat . W2_w[s,:] + W2_b[s] + W1_b[s]; pack sdat
    {
        const float4* W2w4 = (const float4*)W2_w;
        const float4* e4   = (const float4*)ebuf;
        for (int r = 0; r < 32; r++) {
            int s = warp * 32 + r;
            float acc = 0.f;
            #pragma unroll
            for (int i = 0; i < 4; i++) {
                float4 wv = W2w4[s * 128 + lane + 32 * i];
                float4 ev = e4[lane + 32 * i];
                acc += wv.x * ev.x + wv.y * ev.y + wv.z * ev.z + wv.w * ev.w;
            }
            #pragma unroll
            for (int off = 16; off; off >>= 1)
                acc += __shfl_xor_sync(0xffffffffu, acc, off);
            if (lane == 0) {
                float a = acc + W2_b[s] + W1_b[s];
                sdat[s] = make_float4(a, g_w1sum[s], ebuf[2 * s], ebuf[2 * s + 1]);
            }
        }
    }
    __syncthreads();

    // thread roles
    const int d    = t & 127;   // attention: which decoder dim
    const int half = t >> 7;    // attention: which s-half
    // LSTM: thread t owns gates j0=2t, j1=2t+1 (float2 weight loads)
    const float biasA = g_bias[2 * t];
    const float biasB = g_bias[2 * t + 1];
    const float wA0 = W_ih[4 * t + 0], wA1 = W_ih[4 * t + 1];
    const float wB0 = W_ih[4 * t + 2], wB1 = W_ih[4 * t + 3];
    const float2* Wt2 = (const float2*)g_WhhT;   // [d][256 float2]

    for (int step = 0; step < SS; step++) {
        // ---- Phase A: attention (hot loop, MUFU-bound) ----
        const float hd = h_s[d];
        float Z = 0.f, n0 = 0.f, n1 = 0.f;
        const float4* sp = sdat + half * 128;
        #pragma unroll 4
        for (int i = 0; i < 128; i++) {
            float4 v = sp[i];                       // broadcast LDS.128
            float x = fmaf(hd, v.y, v.x);
            float w = __expf(tanh_fast(x));         // 2 MUFU
            Z += w;
            n0 = fmaf(w, v.z, n0);
            n1 = fmaf(w, v.w, n1);
        }
        if (half) red[d] = make_float4(Z, n0, n1, 0.f);
        __syncthreads();

        if (half == 0) {
            float4 r = red[d];
            Z += r.x; n0 += r.y; n1 += r.z;
            float inv = __fdividef(1.f, Z);
            float cx0 = n0 * inv, cx1 = n1 * inv;
            #pragma unroll
            for (int off = 16; off; off >>= 1) {
                cx0 += __shfl_xor_sync(0xffffffffu, cx0, off);
                cx1 += __shfl_xor_sync(0xffffffffu, cx1, off);
            }
            if (lane == 0) { wred[warp][0] = cx0; wred[warp][1] = cx1; }
        }
        __syncthreads();
        if (t == 0) {
            ctx_s[0] = (wred[0][0] + wred[1][0] + wred[2][0] + wred[3][0]) * (1.f / 128.f);
            ctx_s[1] = (wred[0][1] + wred[1][1] + wred[2][1] + wred[3][1]) * (1.f / 128.f);
        }
        __syncthreads();

        // ---- Phase B: LSTM gates (coalesced W_hhT, FMA/L1-bound) ----
        const float x0 = ctx_s[0], x1 = ctx_s[1];
        float accA = fmaf(x0, wA0, fmaf(x1, wA1, biasA));
        float accB = fmaf(x0, wB0, fmaf(x1, wB1, biasB));
        {
            const float4* h4 = (const float4*)h_s;
            #pragma unroll 4
            for (int i = 0; i < 32; i++) {
                float4 hv = h4[i];                          // broadcast
                const float2* wr = Wt2 + (4 * i) * 256 + t; // coalesced
                float2 w0 = wr[0];
                float2 w1 = wr[256];
                float2 w2 = wr[512];
                float2 w3 = wr[768];
                accA = fmaf(hv.x, w0.x, accA); accB = fmaf(hv.x, w0.y, accB);
                accA = fmaf(hv.y, w1.x, accA); accB = fmaf(hv.y, w1.y, accB);
                accA = fmaf(hv.z, w2.x, accA); accB = fmaf(hv.z, w2.y, accB);
                accA = fmaf(hv.w, w3.x, accA); accB = fmaf(hv.w, w3.y, accB);
            }
        }
        gates_s[2 * t]     = accA;
        gates_s[2 * t + 1] = accB;
        __syncthreads();

        // ---- c/h update + output (accurate math here; cheap) ----
        if (t < DD) {
            float gi = gates_s[t];
            float gf = gates_s[t + 128];
            float gg = gates_s[t + 256];
            float go = gates_s[t + 384];
            float si = 1.f / (1.f + __expf(-gi));
            float sf = 1.f / (1.f + __expf(-gf));
            float so = 1.f / (1.f + __expf(-go));
            float c = sf * c_s[t] + si * tanhf(gg);
            float h = so * tanhf(c);
            c_s[t] = c;
            h_s[t] = h;
            out[(size_t)step * (BB * DD) + b * DD + t] = h;
        }
        __syncthreads();
    }
}

// ---------------------------------------------------------------------------
extern "C" void kernel_launch(void* const* d_in, const int* in_sizes, int n_in,
                              void* d_out, int out_size) {
    const float* enc  = (const float*)d_in[0];  // out_encoder [B,S,E]
    const float* W1_w = (const float*)d_in[1];  // [S,S]
    const float* W1_b = (const float*)d_in[2];  // [S]
    const float* W2_w = (const float*)d_in[3];  // [S,2S]
    const float* W2_b = (const float*)d_in[4];  // [S]
    const float* W_ih = (const float*)d_in[5];  // [4D,E]
    const float* W_hh = (const float*)d_in[6];  // [4D,D]
    const float* b_ih = (const float*)d_in[7];  // [4D]
    const float* b_hh = (const float*)d_in[8];  // [4D]
    float* out = (float*)d_out;                 // [S,B,D] f32

    prep_kernel<<<257, 256>>>(W1_w, W_hh, b_ih, b_hh);
    decoder_kernel<<<BB, 256>>>(enc, W1_b, W2_w, W2_b, W_ih, out);
}

// round 2
// speedup vs baseline: 1.2095x; 1.2095x over previous
#include <cuda_runtime.h>
#include <cuda_fp16.h>

#define BB 256   // batch
#define SS 256   // seq len / steps
#define EE 2     // encoder dim
#define DD 128   // decoder dim
#define GG 512   // 4*D gates

// Scratch (__device__ globals; no allocation).
// Packed fp16 LSTM hidden weights: chunk c = d/4 (32 chunks), u = gate-pair
// owner thread (0..255), k = d%4. Element = half2( W_hh[2u][d], W_hh[2u+1][d] ).
// Flat index: c*1024 + u*4 + k. Total 32768 half2 = 128 KB -> L1-resident.
__device__ __align__(16) __half2 g_Wpack[32 * 256 * 4];
__device__ float g_w1sum[SS];
__device__ float g_bias[GG];

__device__ __forceinline__ float tanh_fast(float x) {
    float y;
    asm("tanh.approx.f32 %0, %1;" : "=f"(y) : "f"(x));
    return y;
}
__device__ __forceinline__ float sigmoid_fast(float x) {
    return fmaf(tanh_fast(0.5f * x), 0.5f, 0.5f);
}

// ---------------------------------------------------------------------------
// Prep kernel: pack W_hh to fp16 pairs, row-sum W1_w, fuse biases. One-time.
// ---------------------------------------------------------------------------
__global__ void prep_kernel(const float* __restrict__ W1_w,
                            const float* __restrict__ W_hh,
                            const float* __restrict__ b_ih,
                            const float* __restrict__ b_hh) {
    int blk = blockIdx.x;
    int t = threadIdx.x;
    if (blk < 128) {
        int idx = blk * 256 + t;          // 0..32767
        int c = idx >> 10;                // d-chunk 0..31
        int u = (idx >> 2) & 255;         // gate pair owner
        int k = idx & 3;
        int d = 4 * c + k;
        float lo = W_hh[(2 * u) * DD + d];
        float hi = W_hh[(2 * u + 1) * DD + d];
        g_Wpack[idx] = __halves2half2(__float2half_rn(lo), __float2half_rn(hi));
    } else {
        int lane = t & 31, w = t >> 5;
        for (int r = 0; r < 32; r++) {
            int s = w * 32 + r;
            float acc = 0.f;
            #pragma unroll
            for (int i = 0; i < 8; i++) acc += W1_w[s * SS + lane + 32 * i];
            #pragma unroll
            for (int off = 16; off; off >>= 1)
                acc += __shfl_xor_sync(0xffffffffu, acc, off);
            if (lane == 0) g_w1sum[s] = acc;
        }
        g_bias[t]       = b_ih[t]       + b_hh[t];
        g_bias[t + 256] = b_ih[t + 256] + b_hh[t + 256];
    }
}

// ---------------------------------------------------------------------------
// Main kernel: one CTA per batch element, 256 threads, 256 LSTM steps.
// ---------------------------------------------------------------------------
__global__ __launch_bounds__(256, 2)
void decoder_kernel(const float* __restrict__ enc,   // [B,S,E]
                    const float* __restrict__ W1_b,  // [S]
                    const float* __restrict__ W2_w,  // [S,2S]
                    const float* __restrict__ W2_b,  // [S]
                    const float* __restrict__ W_ih,  // [4D,E]
                    float* __restrict__ out)         // [S,B,D]
{
    __shared__ __align__(16) float4 sdat[SS];      // {a, w1sum, enc0, enc1}
    __shared__ __align__(16) float  ebuf[2 * SS];
    __shared__ __align__(16) float4 red[DD];       // half-1 partials {Z,n0,n1,_}
    __shared__ float gates_s[GG];
    __shared__ __align__(16) float h_s[DD];
    __shared__ float c_s[DD];
    __shared__ __align__(16) float2 wred[4];

    const int b = blockIdx.x;
    const int t = threadIdx.x;
    const int lane = t & 31;
    const int warp = t >> 5;

    // ---- per-b init ----
    ebuf[t]       = enc[b * (2 * SS) + t];
    ebuf[t + 256] = enc[b * (2 * SS) + t + 256];
    if (t < DD) { h_s[t] = 0.f; c_s[t] = 0.f; }
    __syncthreads();

    // a[s] = encflat . W2_w[s,:] + W2_b[s] + W1_b[s]; pack sdat
    {
        const float4* W2w4 = (const float4*)W2_w;
        const float4* e4   = (const float4*)ebuf;
        for (int r = 0; r < 32; r++) {
            int s = warp * 32 + r;
            float acc = 0.f;
            #pragma unroll
            for (int i = 0; i < 4; i++) {
                float4 wv = W2w4[s * 128 + lane + 32 * i];
                float4 ev = e4[lane + 32 * i];
                acc += wv.x * ev.x + wv.y * ev.y + wv.z * ev.z + wv.w * ev.w;
            }
            #pragma unroll
            for (int off = 16; off; off >>= 1)
                acc += __shfl_xor_sync(0xffffffffu, acc, off);
            if (lane == 0) {
                float a = acc + W2_b[s] + W1_b[s];
                sdat[s] = make_float4(a, g_w1sum[s], ebuf[2 * s], ebuf[2 * s + 1]);
            }
        }
    }
    __syncthreads();

    // thread roles
    const int d    = t & 127;   // attention dim
    const int half = t >> 7;    // attention s-half (warp-uniform)
    const float biasA = g_bias[2 * t];
    const float biasB = g_bias[2 * t + 1];
    const float wA0 = W_ih[4 * t + 0], wA1 = W_ih[4 * t + 1];
    const float wB0 = W_ih[4 * t + 2], wB1 = W_ih[4 * t + 3];
    const __half2* wp = g_Wpack + t * 4;

    for (int step = 0; step < SS; step++) {
        // ---- Phase A: attention (MUFU-bound hot loop) ----
        const float hd = h_s[d];
        float Z = 0.f;
        unsigned long long n01 = 0ull;   // packed {n0, n1}
        const float4* sp = sdat + half * 128;
        #pragma unroll 8
        for (int i = 0; i < 128; i++) {
            float4 v = sp[i];                       // broadcast LDS.128
            float x = fmaf(hd, v.y, v.x);
            float w = __expf(tanh_fast(x));         // 2 MUFU + FMUL
            Z += w;
            unsigned long long ww, ee;
            asm("mov.b64 %0, {%1, %1};" : "=l"(ww) : "f"(w));
            asm("mov.b64 %0, {%1, %2};" : "=l"(ee) : "f"(v.z), "f"(v.w));
            asm("fma.rn.f32x2 %0, %1, %2, %0;" : "+l"(n01) : "l"(ww), "l"(ee));
        }
        float n0, n1;
        asm("mov.b64 {%0, %1}, %2;" : "=f"(n0), "=f"(n1) : "l"(n01));

        if (half) red[d] = make_float4(Z, n0, n1, 0.f);
        __syncthreads();                             // B1

        if (half == 0) {
            float4 r = red[d];
            Z += r.x; n0 += r.y; n1 += r.z;
            float inv = __fdividef(1.f, Z);
            float cx0 = n0 * inv, cx1 = n1 * inv;
            #pragma unroll
            for (int off = 16; off; off >>= 1) {
                cx0 += __shfl_xor_sync(0xffffffffu, cx0, off);
                cx1 += __shfl_xor_sync(0xffffffffu, cx1, off);
            }
            if (lane == 0) wred[warp] = make_float2(cx0, cx1);
        }
        __syncthreads();                             // B2

        // every thread computes ctx itself (broadcast LDS, no extra barrier)
        float2 r0 = wred[0], r1 = wred[1], r2 = wred[2], r3 = wred[3];
        const float x0 = (r0.x + r1.x + r2.x + r3.x) * (1.f / 128.f);
        const float x1 = (r0.y + r1.y + r2.y + r3.y) * (1.f / 128.f);

        // ---- Phase B: LSTM gates (fp16 weights, L1-resident) ----
        float accA = fmaf(x0, wA0, fmaf(x1, wA1, biasA));
        float accB = fmaf(x0, wB0, fmaf(x1, wB1, biasB));
        {
            const float4* h4 = (const float4*)h_s;
            #pragma unroll 8
            for (int c = 0; c < 32; c++) {
                float4 hv = h4[c];                              // broadcast
                uint4 wr = *(const uint4*)(wp + c * 1024);      // LDG.128, L1 hit
                float2 f0 = __half22float2(*(const __half2*)&wr.x);
                float2 f1 = __half22float2(*(const __half2*)&wr.y);
                float2 f2 = __half22float2(*(const __half2*)&wr.z);
                float2 f3 = __half22float2(*(const __half2*)&wr.w);
                accA = fmaf(hv.x, f0.x, accA); accB = fmaf(hv.x, f0.y, accB);
                accA = fmaf(hv.y, f1.x, accA); accB = fmaf(hv.y, f1.y, accB);
                accA = fmaf(hv.z, f2.x, accA); accB = fmaf(hv.z, f2.y, accB);
                accA = fmaf(hv.w, f3.x, accA); accB = fmaf(hv.w, f3.y, accB);
            }
        }
        gates_s[2 * t]     = accA;
        gates_s[2 * t + 1] = accB;
        __syncthreads();                             // B3

        // ---- c/h update + output ----
        if (t < DD) {
            float gi = gates_s[t];
            float gf = gates_s[t + 128];
            float gg = gates_s[t + 256];
            float go = gates_s[t + 384];
            float si = sigmoid_fast(gi);
            float sf = sigmoid_fast(gf);
            float so = sigmoid_fast(go);
            float c = fmaf(sf, c_s[t], si * tanh_fast(gg));
            float h = so * tanh_fast(c);
            c_s[t] = c;
            h_s[t] = h;
            out[(size_t)step * (BB * DD) + b * DD + t] = h;
        }
        __syncthreads();                             // B4
    }
}

// ---------------------------------------------------------------------------
extern "C" void kernel_launch(void* const* d_in, const int* in_sizes, int n_in,
                              void* d_out, int out_size) {
    const float* enc  = (const float*)d_in[0];
    const float* W1_w = (const float*)d_in[1];
    const float* W1_b = (const float*)d_in[2];
    const float* W2_w = (const float*)d_in[3];
    const float* W2_b = (const float*)d_in[4];
    const float* W_ih = (const float*)d_in[5];
    const float* W_hh = (const float*)d_in[6];
    const float* b_ih = (const float*)d_in[7];
    const float* b_hh = (const float*)d_in[8];
    float* out = (float*)d_out;

    prep_kernel<<<129, 256>>>(W1_w, W_hh, b_ih, b_hh);
    decoder_kernel<<<BB, 256>>>(enc, W1_b, W2_w, W2_b, W_ih, out);
}